// round 3
// baseline (speedup 1.0000x reference)
#include <cuda_runtime.h>
#include <stdint.h>

#define BB 8
#define NN 16384
#define SS 2048
#define CC 64
#define KK 32
#define COUT (3 + CC)   // 67

// Scratch for ball-query indices (no cudaMalloc allowed).
__device__ __align__(16) int g_idx[BB * SS * KK];

// ---------------------------------------------------------------------------
// Kernel 1: warp-per-center ball query with early exit.
// Reference semantics: smallest 32 indices j with |c-p_j|^2 < 0.04 (ascending),
// padded with the first found index, or 0 if none found.
// ---------------------------------------------------------------------------
__global__ __launch_bounds__(256) void ball_query_kernel(
    const float* __restrict__ points,   // (B, N, 3)
    const float* __restrict__ centers)  // (B, S, 3)
{
    const int wid  = threadIdx.x >> 5;
    const int lane = threadIdx.x & 31;
    const int gw   = blockIdx.x * (blockDim.x >> 5) + wid;  // global warp id = b*S+s
    const int b = gw / SS;
    const int s = gw % SS;

    const float* cptr = centers + (size_t)(b * SS + s) * 3;
    const float cx = __ldg(cptr + 0);
    const float cy = __ldg(cptr + 1);
    const float cz = __ldg(cptr + 2);

    __shared__ int sel[8][KK];   // 8 warps per block

    const float* pbase = points + (size_t)b * NN * 3;
    const float R2 = 0.04f;     // float(0.2**2), matches f32 rounding of the ref

    int cnt = 0;
    for (int t = 0; t < NN / 32; ++t) {
        const int j = t * 32 + lane;
        const float px = __ldg(pbase + 3 * j + 0);
        const float py = __ldg(pbase + 3 * j + 1);
        const float pz = __ldg(pbase + 3 * j + 2);
        // No FMA contraction: match XLA's sub/square/sequential-sum ordering.
        const float dx = __fadd_rn(cx, -px);
        const float dy = __fadd_rn(cy, -py);
        const float dz = __fadd_rn(cz, -pz);
        const float d2 = __fadd_rn(__fadd_rn(__fmul_rn(dx, dx), __fmul_rn(dy, dy)),
                                   __fmul_rn(dz, dz));
        const bool hit = d2 < R2;
        const unsigned m = __ballot_sync(0xffffffffu, hit);
        if (hit) {
            const int pos = cnt + __popc(m & ((1u << lane) - 1u));
            if (pos < KK) sel[wid][pos] = j;
        }
        cnt += __popc(m);
        if (cnt >= KK) break;   // warp-uniform early exit
    }
    __syncwarp();

    int v;
    if (cnt == 0) {
        v = 0;
    } else {
        const int first = sel[wid][0];
        v = (lane < cnt) ? sel[wid][lane] : first;
    }
    g_idx[(size_t)gw * KK + lane] = v;   // coalesced 128B per warp
}

// ---------------------------------------------------------------------------
// Kernel 2: one block per (b, out-channel) plane.
// Stage the 64KB source row in shared memory, gather via LDS, coalesced
// float4 stores. co<3 -> points component (minus center), co>=3 -> feature row.
// ---------------------------------------------------------------------------
__global__ __launch_bounds__(512) void gather_kernel(
    const float* __restrict__ points,   // (B, N, 3)
    const float* __restrict__ centers,  // (B, S, 3)
    const float* __restrict__ feats,    // (B, C, N)
    float* __restrict__ out)            // (B, 67, S, K)
{
    extern __shared__ float row[];      // NN floats = 64KB

    const int plane = blockIdx.x;       // 0 .. B*67-1
    const int b  = plane / COUT;
    const int co = plane % COUT;
    const bool isxyz = (co < 3);

    if (isxyz) {
        const float* p = points + (size_t)b * NN * 3 + co;
        for (int i = threadIdx.x; i < NN; i += blockDim.x)
            row[i] = __ldg(p + 3 * i);
    } else {
        const float4* f4 = (const float4*)(feats + ((size_t)b * CC + (co - 3)) * NN);
        float4* r4 = (float4*)row;
        for (int i = threadIdx.x; i < NN / 4; i += blockDim.x)
            r4[i] = __ldg(f4 + i);
    }
    __syncthreads();

    const int4*  idx4 = (const int4*)(g_idx + (size_t)b * SS * KK);
    float4*      out4 = (float4*)(out + (size_t)plane * SS * KK);
    const float* cbase = centers + (size_t)b * SS * 3 + co;

    const int total4 = SS * KK / 4;     // 16384 float4 per plane
    for (int i = threadIdx.x; i < total4; i += blockDim.x) {
        const int4 id = __ldg(idx4 + i);
        float4 v;
        v.x = row[id.x];
        v.y = row[id.y];
        v.z = row[id.z];
        v.w = row[id.w];
        if (isxyz) {
            const int s = i >> 3;       // 8 groups of 4 per center (K=32)
            const float cv = __ldg(cbase + 3 * s);
            v.x -= cv; v.y -= cv; v.z -= cv; v.w -= cv;
        }
        out4[i] = v;
    }
}

// ---------------------------------------------------------------------------
extern "C" void kernel_launch(void* const* d_in, const int* in_sizes, int n_in,
                              void* d_out, int out_size)
{
    const float* points  = (const float*)d_in[0];  // 8*16384*3
    const float* centers = (const float*)d_in[1];  // 8*2048*3
    const float* feats   = (const float*)d_in[2];  // 8*64*16384
    float* out = (float*)d_out;                    // 8*67*2048*32

    (void)in_sizes; (void)n_in; (void)out_size;

    // 64KB dynamic smem needs the opt-in attribute (not a stream op; capture-safe).
    static_assert(NN * sizeof(float) == 65536, "row size");
    cudaFuncSetAttribute(gather_kernel,
                         cudaFuncAttributeMaxDynamicSharedMemorySize,
                         NN * (int)sizeof(float));

    // Kernel 1: 16384 warps, 8 per block.
    ball_query_kernel<<<BB * SS / 8, 256>>>(points, centers);

    // Kernel 2: one block per output plane.
    gather_kernel<<<BB * COUT, 512, NN * sizeof(float)>>>(points, centers, feats, out);
}

// round 5
// speedup vs baseline: 1.9081x; 1.9081x over previous
#include <cuda_runtime.h>
#include <stdint.h>

#define BB 8
#define NN 16384
#define SS 2048
#define CC 64
#define KK 32
#define COUT (3 + CC)   // 67
#define NG  (NN / 128)  // 128 groups of 128 points

// Scratch for ball-query indices (no cudaMalloc allowed).
__device__ __align__(16) int g_idx[BB * SS * KK];

// ---------------------------------------------------------------------------
// Kernel 1: warp-per-center ball query, 128 points per iteration,
// software-prefetched loads, 4 independent ballots per iteration.
// Semantics: smallest 32 indices j with |c-p_j|^2 < 0.04 (ascending),
// padded with the first found index, or 0 if none found.
// ---------------------------------------------------------------------------
__global__ __launch_bounds__(256) void ball_query_kernel(
    const float4* __restrict__ points4,  // (B, N, 3) viewed as float4
    const float*  __restrict__ centers)  // (B, S, 3)
{
    const int wid  = threadIdx.x >> 5;
    const int lane = threadIdx.x & 31;
    const int gw   = blockIdx.x * (blockDim.x >> 5) + wid;  // b*S + s
    const int b = gw / SS;

    const float* cptr = centers + (size_t)gw * 3;
    const float cx = __ldg(cptr + 0);
    const float cy = __ldg(cptr + 1);
    const float cz = __ldg(cptr + 2);

    __shared__ int sel[8][KK];

    // points for batch b in float4 units: NN*3/4 = 12288 float4 per batch
    const float4* pb = points4 + (size_t)b * (NN * 3 / 4);
    const float R2 = 0.04f;
    const unsigned below = (1u << lane) - 1u;

    int cnt = 0;

    // prefetch group 0
    float4 a0 = __ldg(pb + 3 * lane + 0);
    float4 a1 = __ldg(pb + 3 * lane + 1);
    float4 a2 = __ldg(pb + 3 * lane + 2);

    for (int g = 0; g < NG; ++g) {
        // prefetch next group before touching current data
        float4 b0 = make_float4(0.f, 0.f, 0.f, 0.f);
        float4 b1 = b0, b2 = b0;
        if (g + 1 < NG) {
            const float4* nb = pb + (size_t)(g + 1) * 96 + 3 * lane;
            b0 = __ldg(nb + 0); b1 = __ldg(nb + 1); b2 = __ldg(nb + 2);
        }

        // unpack 4 AoS points from the 3 float4s
        // p0=(a0.x,a0.y,a0.z) p1=(a0.w,a1.x,a1.y) p2=(a1.z,a1.w,a2.x) p3=(a2.y,a2.z,a2.w)
        float dx, dy, dz;
        #define DIST(PX,PY,PZ,DST)                                            \
            dx = __fadd_rn(cx, -(PX)); dy = __fadd_rn(cy, -(PY));             \
            dz = __fadd_rn(cz, -(PZ));                                        \
            DST = __fadd_rn(__fadd_rn(__fmul_rn(dx,dx), __fmul_rn(dy,dy)),    \
                            __fmul_rn(dz,dz));
        float q0, q1, q2, q3;
        DIST(a0.x, a0.y, a0.z, q0);
        DIST(a0.w, a1.x, a1.y, q1);
        DIST(a1.z, a1.w, a2.x, q2);
        DIST(a2.y, a2.z, a2.w, q3);
        #undef DIST

        const bool h0 = q0 < R2, h1 = q1 < R2, h2 = q2 < R2, h3 = q3 < R2;
        const unsigned m0 = __ballot_sync(0xffffffffu, h0);
        const unsigned m1 = __ballot_sync(0xffffffffu, h1);
        const unsigned m2 = __ballot_sync(0xffffffffu, h2);
        const unsigned m3 = __ballot_sync(0xffffffffu, h3);

        // lane-major index order: j = g*128 + 4*lane + c
        int p = cnt + __popc(m0 & below) + __popc(m1 & below)
                    + __popc(m2 & below) + __popc(m3 & below);
        const int j = g * 128 + 4 * lane;
        if (h0) { if (p < KK) sel[wid][p] = j + 0; p++; }
        if (h1) { if (p < KK) sel[wid][p] = j + 1; p++; }
        if (h2) { if (p < KK) sel[wid][p] = j + 2; p++; }
        if (h3) { if (p < KK) sel[wid][p] = j + 3; p++; }

        cnt += __popc(m0) + __popc(m1) + __popc(m2) + __popc(m3);
        if (cnt >= KK) break;   // warp-uniform

        a0 = b0; a1 = b1; a2 = b2;
    }
    __syncwarp();

    int v;
    if (cnt == 0) {
        v = 0;
    } else {
        const int first = sel[wid][0];
        v = (lane < cnt) ? sel[wid][lane] : first;
    }
    g_idx[(size_t)gw * KK + lane] = v;
}

// ---------------------------------------------------------------------------
// Kernel 2: one block per (b, out-channel) plane; 64KB smem row stage;
// 4-way unrolled independent gather iterations for MLP.
// ---------------------------------------------------------------------------
__global__ __launch_bounds__(512) void gather_kernel(
    const float* __restrict__ points,   // (B, N, 3)
    const float* __restrict__ centers,  // (B, S, 3)
    const float* __restrict__ feats,    // (B, C, N)
    float* __restrict__ out)            // (B, 67, S, K)
{
    extern __shared__ float row[];      // NN floats = 64KB

    const int plane = blockIdx.x;       // 0 .. B*67-1
    const int b  = plane / COUT;
    const int co = plane % COUT;
    const bool isxyz = (co < 3);

    if (isxyz) {
        const float* p = points + (size_t)b * NN * 3 + co;
        for (int i = threadIdx.x; i < NN; i += blockDim.x)
            row[i] = __ldg(p + 3 * i);
    } else {
        const float4* f4 = (const float4*)(feats + ((size_t)b * CC + (co - 3)) * NN);
        float4* r4 = (float4*)row;
        for (int i = threadIdx.x; i < NN / 4; i += blockDim.x)
            r4[i] = __ldg(f4 + i);
    }
    __syncthreads();

    const int4*  idx4 = (const int4*)(g_idx + (size_t)b * SS * KK);
    float4*      out4 = (float4*)(out + (size_t)plane * SS * KK);
    const float* cbase = centers + (size_t)b * SS * 3 + co;

    // total4 = SS*KK/4 = 16384; 512 threads -> 32 iters; do 8 outer x 4 unrolled
    #pragma unroll 1
    for (int ii = 0; ii < 8; ++ii) {
        const int i0 = ii * 2048 + threadIdx.x;
        const int i1 = i0 + 512, i2 = i0 + 1024, i3 = i0 + 1536;

        // 4 independent idx loads
        const int4 d0 = __ldg(idx4 + i0);
        const int4 d1 = __ldg(idx4 + i1);
        const int4 d2 = __ldg(idx4 + i2);
        const int4 d3 = __ldg(idx4 + i3);

        // 16 independent shared gathers
        float4 v0, v1, v2, v3;
        v0.x = row[d0.x]; v0.y = row[d0.y]; v0.z = row[d0.z]; v0.w = row[d0.w];
        v1.x = row[d1.x]; v1.y = row[d1.y]; v1.z = row[d1.z]; v1.w = row[d1.w];
        v2.x = row[d2.x]; v2.y = row[d2.y]; v2.z = row[d2.z]; v2.w = row[d2.w];
        v3.x = row[d3.x]; v3.y = row[d3.y]; v3.z = row[d3.z]; v3.w = row[d3.w];

        if (isxyz) {
            const float c0 = __ldg(cbase + 3 * (i0 >> 3));
            const float c1 = __ldg(cbase + 3 * (i1 >> 3));
            const float c2 = __ldg(cbase + 3 * (i2 >> 3));
            const float c3 = __ldg(cbase + 3 * (i3 >> 3));
            v0.x -= c0; v0.y -= c0; v0.z -= c0; v0.w -= c0;
            v1.x -= c1; v1.y -= c1; v1.z -= c1; v1.w -= c1;
            v2.x -= c2; v2.y -= c2; v2.z -= c2; v2.w -= c2;
            v3.x -= c3; v3.y -= c3; v3.z -= c3; v3.w -= c3;
        }

        out4[i0] = v0;
        out4[i1] = v1;
        out4[i2] = v2;
        out4[i3] = v3;
    }
}

// ---------------------------------------------------------------------------
extern "C" void kernel_launch(void* const* d_in, const int* in_sizes, int n_in,
                              void* d_out, int out_size)
{
    const float* points  = (const float*)d_in[0];  // 8*16384*3
    const float* centers = (const float*)d_in[1];  // 8*2048*3
    const float* feats   = (const float*)d_in[2];  // 8*64*16384
    float* out = (float*)d_out;                    // 8*67*2048*32

    (void)in_sizes; (void)n_in; (void)out_size;

    static_assert(NN * sizeof(float) == 65536, "row size");
    cudaFuncSetAttribute(gather_kernel,
                         cudaFuncAttributeMaxDynamicSharedMemorySize,
                         NN * (int)sizeof(float));

    ball_query_kernel<<<BB * SS / 8, 256>>>((const float4*)points, centers);
    gather_kernel<<<BB * COUT, 512, NN * sizeof(float)>>>(points, centers, feats, out);
}